// round 1
// baseline (speedup 1.0000x reference)
#include <cuda_runtime.h>

// AlphaCompositor: N=8, K=8, H=512, W=512, C=4, P=100000
// out = [images (N,C,H,W) f32] ++ [!bg_mask (N,H,W) as f32]

#define NN 8
#define KK 8
#define HH 512
#define WW 512
#define CC 4
#define PP 100000
#define HW (HH * WW)

// Scratch: AoS-packed point features, one float4 per point (1.6 MB, L2-resident).
__device__ float4 g_packed[PP];

__global__ void pack_kernel(const float* __restrict__ ptclds) {
    int p = blockIdx.x * blockDim.x + threadIdx.x;
    if (p < PP) {
        float4 v;
        v.x = __ldg(ptclds + 0 * PP + p);
        v.y = __ldg(ptclds + 1 * PP + p);
        v.z = __ldg(ptclds + 2 * PP + p);
        v.w = __ldg(ptclds + 3 * PP + p);
        g_packed[p] = v;
    }
}

// One thread handles 4 adjacent pixels along W (all vector accesses 16B-aligned).
__global__ __launch_bounds__(256) void composite_kernel(
    const int*   __restrict__ pix,
    const float* __restrict__ alphas,
    float*       __restrict__ out,
    int write_mask)
{
    const int t     = blockIdx.x * blockDim.x + threadIdx.x;
    const int total = NN * HW / 4;
    if (t >= total) return;

    const int base = t * 4;          // linear pixel index within N*H*W
    const int n    = base / HW;
    const int hw   = base % HW;
    const long nbase = (long)n * KK * HW + hw;

    // per-pixel state
    float4 acc[4];
    float  trans[4];
    bool   bg[4];
#pragma unroll
    for (int i = 0; i < 4; i++) {
        acc[i]   = make_float4(0.f, 0.f, 0.f, 0.f);
        trans[i] = 1.0f;
    }

    // k = 0: also determines background status
    {
        int4   idx = *reinterpret_cast<const int4*>(pix + nbase);
        float4 al  = *reinterpret_cast<const float4*>(alphas + nbase);
        const int   iv[4] = {idx.x, idx.y, idx.z, idx.w};
        const float av[4] = {al.x, al.y, al.z, al.w};
#pragma unroll
        for (int i = 0; i < 4; i++) {
            bg[i] = (iv[i] < 0);
            if (!bg[i]) {
                float4 f = g_packed[iv[i]];
                float  w = av[i] * trans[i];
                acc[i].x += w * f.x; acc[i].y += w * f.y;
                acc[i].z += w * f.z; acc[i].w += w * f.w;
                trans[i] *= (1.0f - av[i]);
            }
        }
    }

#pragma unroll
    for (int k = 1; k < KK; k++) {
        int4   idx = *reinterpret_cast<const int4*>(pix + nbase + (long)k * HW);
        float4 al  = *reinterpret_cast<const float4*>(alphas + nbase + (long)k * HW);
        const int   iv[4] = {idx.x, idx.y, idx.z, idx.w};
        const float av[4] = {al.x, al.y, al.z, al.w};
#pragma unroll
        for (int i = 0; i < 4; i++) {
            if (iv[i] >= 0) {
                float4 f = g_packed[iv[i]];
                float  w = av[i] * trans[i];
                acc[i].x += w * f.x; acc[i].y += w * f.y;
                acc[i].z += w * f.z; acc[i].w += w * f.w;
                trans[i] *= (1.0f - av[i]);
            }
        }
    }

    // Background override: images = (0,0,0,1)
#pragma unroll
    for (int i = 0; i < 4; i++) {
        if (bg[i]) acc[i] = make_float4(0.f, 0.f, 0.f, 1.f);
    }

    // Store images [N,C,H,W]: per channel, a float4 across the 4 w-pixels.
    const long obase = (long)n * CC * HW + hw;
    float4 vc;
    vc = make_float4(acc[0].x, acc[1].x, acc[2].x, acc[3].x);
    *reinterpret_cast<float4*>(out + obase + 0L * HW) = vc;
    vc = make_float4(acc[0].y, acc[1].y, acc[2].y, acc[3].y);
    *reinterpret_cast<float4*>(out + obase + 1L * HW) = vc;
    vc = make_float4(acc[0].z, acc[1].z, acc[2].z, acc[3].z);
    *reinterpret_cast<float4*>(out + obase + 2L * HW) = vc;
    vc = make_float4(acc[0].w, acc[1].w, acc[2].w, acc[3].w);
    *reinterpret_cast<float4*>(out + obase + 3L * HW) = vc;

    // Mask output (!bg) as float, appended after images.
    if (write_mask) {
        float4 m = make_float4(bg[0] ? 0.f : 1.f, bg[1] ? 0.f : 1.f,
                               bg[2] ? 0.f : 1.f, bg[3] ? 0.f : 1.f);
        *reinterpret_cast<float4*>(out + (long)NN * CC * HW + base) = m;
    }
}

extern "C" void kernel_launch(void* const* d_in, const int* in_sizes, int n_in,
                              void* d_out, int out_size) {
    const int*   pix    = (const int*)d_in[0];    // pix_idxs int32 [N,K,H,W]
    const float* alphas = (const float*)d_in[1];  // alphas  f32   [N,K,H,W]
    const float* ptclds = (const float*)d_in[2];  // ptclds  f32   [C,P]
    float* out = (float*)d_out;

    const int images_elems = NN * CC * HW;
    const int write_mask   = (out_size > images_elems) ? 1 : 0;

    pack_kernel<<<(PP + 255) / 256, 256>>>(ptclds);

    const int total_threads = NN * HW / 4;   // 524288
    composite_kernel<<<total_threads / 256, 256>>>(pix, alphas, out, write_mask);
}

// round 4
// speedup vs baseline: 1.0304x; 1.0304x over previous
#include <cuda_runtime.h>

// AlphaCompositor: N=8, K=8, H=512, W=512, C=4, P=100000
// out = [images (N,C,H,W) f32] ++ [!bg_mask (N,H,W) as f32]

#define NN 8
#define KK 8
#define HH 512
#define WW 512
#define CC 4
#define PP 100000
#define HW (HH * WW)

// Scratch: AoS-packed point features, one float4 per point (1.6 MB, L2-resident).
__device__ float4 g_packed[PP];

__global__ void pack_kernel(const float* __restrict__ ptclds) {
    int p = blockIdx.x * blockDim.x + threadIdx.x;
    if (p < PP) {
        float4 v;
        v.x = __ldg(ptclds + 0 * PP + p);
        v.y = __ldg(ptclds + 1 * PP + p);
        v.z = __ldg(ptclds + 2 * PP + p);
        v.w = __ldg(ptclds + 3 * PP + p);
        g_packed[p] = v;
    }
}

// One pixel per thread: minimal registers -> high occupancy -> many
// independent gather streams in flight to saturate L1tex wavefront throughput.
__global__ __launch_bounds__(256) void composite_kernel(
    const int*   __restrict__ pix,
    const float* __restrict__ alphas,
    float*       __restrict__ out,
    int write_mask)
{
    const int t = blockIdx.x * blockDim.x + threadIdx.x;   // pixel id in [0, N*HW)
    const int n  = t >> 18;          // / HW  (HW = 262144 = 2^18)
    const int hw = t & (HW - 1);
    const long nbase = (long)n * KK * HW + hw;

    // ---- Phase 1: load all indices + alphas (streaming, coalesced) ----
    int   idx[KK];
    float al[KK];
#pragma unroll
    for (int k = 0; k < KK; k++) {
        idx[k] = __ldg(pix    + nbase + (long)k * HW);
        al[k]  = __ldg(alphas + nbase + (long)k * HW);
    }

    // ---- Phase 2: weights (pure FMA chain, no memory) ----
    float w[KK];
    {
        float trans = 1.0f;
#pragma unroll
        for (int k = 0; k < KK; k++) {
            float a = (idx[k] >= 0) ? al[k] : 0.0f;
            w[k] = a * trans;
            trans *= (1.0f - a);
        }
    }

    // ---- Phase 3: gather + accumulate (8 independent gathers in flight) ----
    float ax = 0.f, ay = 0.f, az = 0.f, aw = 0.f;
#pragma unroll
    for (int k = 0; k < KK; k++) {
        if (idx[k] >= 0) {
            float4 f = __ldg(&g_packed[idx[k]]);
            ax = fmaf(w[k], f.x, ax);
            ay = fmaf(w[k], f.y, ay);
            az = fmaf(w[k], f.z, az);
            aw = fmaf(w[k], f.w, aw);
        }
    }

    // Background pixel: first index negative -> images = BG = (0,0,0,1)
    const bool bg = (idx[0] < 0);
    if (bg) { ax = 0.f; ay = 0.f; az = 0.f; aw = 1.f; }

    // ---- Stores: [N,C,H,W] images, then mask ----
    const long obase = (long)n * CC * HW + hw;
    out[obase + 0L * HW] = ax;
    out[obase + 1L * HW] = ay;
    out[obase + 2L * HW] = az;
    out[obase + 3L * HW] = aw;

    if (write_mask) {
        out[(long)NN * CC * HW + t] = bg ? 0.f : 1.f;
    }
}

extern "C" void kernel_launch(void* const* d_in, const int* in_sizes, int n_in,
                              void* d_out, int out_size) {
    const int*   pix    = (const int*)d_in[0];    // pix_idxs int32 [N,K,H,W]
    const float* alphas = (const float*)d_in[1];  // alphas  f32   [N,K,H,W]
    const float* ptclds = (const float*)d_in[2];  // ptclds  f32   [C,P]
    float* out = (float*)d_out;

    const int images_elems = NN * CC * HW;
    const int write_mask   = (out_size > images_elems) ? 1 : 0;

    pack_kernel<<<(PP + 255) / 256, 256>>>(ptclds);

    const int total_threads = NN * HW;   // 2097152
    composite_kernel<<<total_threads / 256, 256>>>(pix, alphas, out, write_mask);
}